// round 16
// baseline (speedup 1.0000x reference)
#include <cuda_runtime.h>
#include <cuda_fp16.h>
#include <math.h>
#include <stdint.h>

// Problem dims
#define T_ 160
#define B_ 256
#define H_ 256
#define G_ 1024   // 4H
#define K_ 512    // Cin for both layers

// ---------------- scratch (device globals) ----------------------------------
__device__ __half g_xr [(size_t)T_ * B_ * K_];    // x -> fp16, k16-permuted
__device__ __half g_wr [4][(size_t)G_ * K_];      // Wih l0f,l0b,l1f,l1b fp16, permuted
__device__ float  g_xgf[(size_t)T_ * G_ * B_];    // [T,4H,B] fwd (fp32 gates)
__device__ float  g_xgb[(size_t)T_ * G_ * B_];    // [T,4H,B] bwd
__device__ __half g_h0 [(size_t)T_ * B_ * 512];   // layer-0 out, fp16, permuted
__device__ __half g_hst[2][2][B_][H_];            // h state fp16 [buf][dir][b][k]
__device__ unsigned g_rcnt[8][32];                // gen-barrier (proven R4/R6/R7)
__device__ volatile unsigned g_rgen[8][32];

// ---------------- helpers ---------------------------------------------------
__device__ __forceinline__ void mma_f16(float c[4], const uint32_t a[4], const uint32_t b[2]) {
    asm volatile(
        "mma.sync.aligned.m16n8k16.row.col.f32.f16.f16.f32 "
        "{%0,%1,%2,%3}, {%4,%5,%6,%7}, {%8,%9}, {%0,%1,%2,%3};"
        : "+f"(c[0]), "+f"(c[1]), "+f"(c[2]), "+f"(c[3])
        : "r"(a[0]), "r"(a[1]), "r"(a[2]), "r"(a[3]), "r"(b[0]), "r"(b[1]));
}
__device__ __forceinline__ uint32_t cvta_s(const void* p) {
    return (uint32_t)__cvta_generic_to_shared(p);
}
__device__ __forceinline__ void cp16(uint32_t s, const void* g) {
    asm volatile("cp.async.cg.shared.global [%0], [%1], 16;\n" :: "r"(s), "l"(g));
}
#define CP_COMMIT() asm volatile("cp.async.commit_group;\n")
#define CP_WAIT0()  asm volatile("cp.async.wait_group 0;\n")
#define CP_WAIT1()  asm volatile("cp.async.wait_group 1;\n")

__device__ __forceinline__ float sigm_f(float x) {
    return __fdividef(1.f, 1.f + __expf(-x));
}
__device__ __forceinline__ float tanh_f(float x) {
    float e = __expf(2.f * x);
    return (e - 1.f) * __fdividef(1.f, e + 1.f);
}
__device__ __forceinline__ uint32_t h2u(float a, float b) {
    __half2 h = __floats2half2_rn(a, b);
    return *(uint32_t*)&h;
}

// 16-CTA group barrier (CTAs sharing dir+batch-tile) — proven R4/R6/R7
__device__ __forceinline__ void group_barrier(int grp) {
    __syncthreads();
    if (threadIdx.x == 0) {
        unsigned gen = g_rgen[grp][0];
        __threadfence();
        if (atomicAdd(&g_rcnt[grp][0], 1) == 15) {
            g_rcnt[grp][0] = 0;
            __threadfence();
            g_rgen[grp][0] = gen + 1;
        } else {
            while (g_rgen[grp][0] == gen) { }
        }
        __threadfence();
    }
    __syncthreads();
}

// ---------------- prep: fp16-convert x + Wih with k16 permutation -----------
__device__ __forceinline__ void perm_store8(__half* dst, const float* src16, int q0) {
    __half h[8];
    int t0 = q0 >> 2;
    #pragma unroll
    for (int j = 0; j < 2; j++) {
        int t = t0 + j;
        h[j*4+0] = __float2half_rn(src16[2*t]);
        h[j*4+1] = __float2half_rn(src16[2*t+1]);
        h[j*4+2] = __float2half_rn(src16[8+2*t]);
        h[j*4+3] = __float2half_rn(src16[9+2*t]);
    }
    *(uint4*)(dst + q0) = *(uint4*)h;
}

__global__ void prep_round(const float* __restrict__ x,
                           const float* __restrict__ w0f, const float* __restrict__ w0b,
                           const float* __restrict__ w1f, const float* __restrict__ w1b)
{
    size_t i0 = (size_t)blockIdx.x * blockDim.x + threadIdx.x;
    size_t stride = (size_t)gridDim.x * blockDim.x;
    const size_t NX8 = (size_t)T_ * B_ * K_ / 8;
    const size_t NW8 = (size_t)G_ * K_ / 8;
    for (size_t e = i0; e < NX8; e += stride) {
        size_t row = e >> 6;
        int off8 = (int)(e & 63) * 8;
        int blk = off8 >> 4, sub = off8 & 15;
        perm_store8(g_xr + row * K_ + blk * 16, x + row * K_ + blk * 16, sub);
    }
    const float* ws[4] = { w0f, w0b, w1f, w1b };
    #pragma unroll
    for (int l = 0; l < 4; l++) {
        for (size_t e = i0; e < NW8; e += stride) {
            size_t row = e >> 6;
            int off8 = (int)(e & 63) * 8;
            int blk = off8 >> 4, sub = off8 & 15;
            perm_store8(g_wr[l] + row * K_ + blk * 16, ws[l] + row * K_ + blk * 16, sub);
        }
    }
}

// ---------------- input GEMM: fp16 m16n8k16, warp 64x64, 3-stage ------------
// GS2=40 (80B row pitch): gid stride = 20 banks mod 32 -> all 8 rows hit
// distinct bank groups -> conflict-free LDS.64 fragment loads.
#define GS2 40
#define GEMM_STAGE (2 * 128 * GS2)
#define GEMM_SMEM (3 * GEMM_STAGE * 2)

__global__ __launch_bounds__(128, 2) void gemm_xg(
    int layer,
    const float* __restrict__ bif, const float* __restrict__ bhf,
    const float* __restrict__ bib, const float* __restrict__ bhb)
{
    extern __shared__ __half gsm[];
    const __half* X = layer ? g_h0 : g_xr;

    int t  = blockIdx.z;
    int jt = blockIdx.y;
    int bt = blockIdx.x;
    int dir = jt >> 3;
    int j0  = (jt & 7) * 128;
    int b0  = bt * 128;
    const __half* W  = g_wr[layer * 2 + dir];
    const float* bi = dir ? bib : bif;
    const float* bh = dir ? bhb : bhf;
    float* out = dir ? g_xgb : g_xgf;

    int tid  = threadIdx.x;
    int wid  = tid >> 5;
    int lane = tid & 31;
    int gid  = lane >> 2;
    int tig  = lane & 3;
    int m0   = (wid >> 1) * 64;
    int n0   = (wid & 1) * 64;

    const __half* Xb = X + ((size_t)t * B_ + b0) * K_;
    const __half* Wb = W + (size_t)j0 * K_;

    float acc[4][8][4];
    #pragma unroll
    for (int mi = 0; mi < 4; mi++)
        #pragma unroll
        for (int ni = 0; ni < 8; ni++)
            #pragma unroll
            for (int r = 0; r < 4; r++) acc[mi][ni][r] = 0.f;

    #pragma unroll
    for (int ps = 0; ps < 2; ps++) {
        __half* As = gsm + ps * GEMM_STAGE;
        __half* Bs = As + 128 * GS2;
        int k0 = ps * 32;
        #pragma unroll
        for (int i = 0; i < 4; i++) {
            int e = tid + i * 128;
            int row = e >> 2, c = e & 3;
            cp16(cvta_s(As + row * GS2 + c * 8), Wb + (size_t)row * K_ + k0 + c * 8);
            cp16(cvta_s(Bs + row * GS2 + c * 8), Xb + (size_t)row * K_ + k0 + c * 8);
        }
        CP_COMMIT();
    }

    for (int s = 0; s < 16; s++) {
        if (s < 15) { CP_WAIT1(); } else { CP_WAIT0(); }
        __syncthreads();

        if (s + 2 < 16) {
            int k0 = (s + 2) * 32;
            __half* As = gsm + ((s + 2) % 3) * GEMM_STAGE;
            __half* Bs = As + 128 * GS2;
            #pragma unroll
            for (int i = 0; i < 4; i++) {
                int e = tid + i * 128;
                int row = e >> 2, c = e & 3;
                cp16(cvta_s(As + row * GS2 + c * 8), Wb + (size_t)row * K_ + k0 + c * 8);
                cp16(cvta_s(Bs + row * GS2 + c * 8), Xb + (size_t)row * K_ + k0 + c * 8);
            }
            CP_COMMIT();
        }

        const __half* As = gsm + (s % 3) * GEMM_STAGE;
        const __half* Bs = As + 128 * GS2;

        #pragma unroll
        for (int c = 0; c < 2; c++) {
            uint32_t a[4][4];
            #pragma unroll
            for (int mi = 0; mi < 4; mi++) {
                uint2 al = *(const uint2*)(As + (m0 + mi*16 + gid    ) * GS2 + c*16 + tig*4);
                uint2 ah = *(const uint2*)(As + (m0 + mi*16 + gid + 8) * GS2 + c*16 + tig*4);
                a[mi][0] = al.x; a[mi][1] = ah.x; a[mi][2] = al.y; a[mi][3] = ah.y;
            }
            uint32_t b[8][2];
            #pragma unroll
            for (int ni = 0; ni < 8; ni++) {
                uint2 bv = *(const uint2*)(Bs + (n0 + ni*8 + gid) * GS2 + c*16 + tig*4);
                b[ni][0] = bv.x; b[ni][1] = bv.y;
            }
            #pragma unroll
            for (int mi = 0; mi < 4; mi++)
                #pragma unroll
                for (int ni = 0; ni < 8; ni++)
                    mma_f16(acc[mi][ni], a[mi], b[ni]);
        }
    }

    #pragma unroll
    for (int mi = 0; mi < 4; mi++) {
        int j_lo = j0 + m0 + mi * 16 + gid;
        int j_hi = j_lo + 8;
        float bs_lo = bi[j_lo] + bh[j_lo];
        float bs_hi = bi[j_hi] + bh[j_hi];
        #pragma unroll
        for (int ni = 0; ni < 8; ni++) {
            int bc = b0 + n0 + ni * 8 + 2 * tig;
            float2 lo = make_float2(acc[mi][ni][0] + bs_lo, acc[mi][ni][1] + bs_lo);
            float2 hi = make_float2(acc[mi][ni][2] + bs_hi, acc[mi][ni][3] + bs_hi);
            *(float2*)(out + ((size_t)t * G_ + j_lo) * B_ + bc) = lo;
            *(float2*)(out + ((size_t)t * G_ + j_hi) * B_ + bc) = hi;
        }
    }
}

// ---------------- recurrence: fp16 MMA, gen-barrier sync (R7 verbatim) ------
// 128 CTAs: dir=bid>>6, ug=(bid>>2)&15 (16 units), bt=bid&3 (64 batch).
#define HS2 264                                  // halves per Hs row
#define XSF 68                                   // floats per XGs row
#define HS_BYTES (64 * HS2 * 2)                  // 33792
#define REC_SMEM (HS_BYTES + 64 * XSF * 4)       // + 17408 = 51200

__global__ void __launch_bounds__(256, 1) lstm_rec_mma(
    const float* __restrict__ Whhf, const float* __restrict__ Whhb,
    float* __restrict__ out_ext, int to_ext)
{
    extern __shared__ __align__(16) char sm[];
    __half* Hs  = (__half*)sm;                   // [64 b][HS2]
    float*  XGs = (float*)(sm + HS_BYTES);       // [64 gate-row][XSF]
    float*  Acc = (float*)sm;                    // alias over Hs after MMA  [64][XSF]

    int bid = blockIdx.x;
    int dir = bid >> 6;
    int ug  = (bid >> 2) & 15;
    int bt  = bid & 3;
    int b0  = bt * 64;
    int grp = dir * 4 + bt;
    int tid = threadIdx.x;
    int wid = tid >> 5, lane = tid & 31, gid = lane >> 2, tig = lane & 3;
    int m0 = (wid >> 1) * 16;
    int n0 = (wid & 1) * 32;
    const float* Whh = dir ? Whhb : Whhf;
    const float* xg  = dir ? g_xgb : g_xgf;

    // W fragments -> registers as fp16 (rounded once). 16 k16-chunks x 4 regs.
    uint32_t A0[16], A1[16], A2[16], A3[16];
    {
        int rl = m0 + gid, rh = rl + 8;
        const float* wl = Whh + (size_t)((rl >> 4) * H_ + ug * 16 + (rl & 15)) * H_;
        const float* wh = Whh + (size_t)((rh >> 4) * H_ + ug * 16 + (rh & 15)) * H_;
        #pragma unroll
        for (int c = 0; c < 16; c++) {
            int k0 = c * 16 + 2 * tig;
            A0[c] = h2u(wl[k0],     wl[k0 + 1]);
            A1[c] = h2u(wh[k0],     wh[k0 + 1]);
            A2[c] = h2u(wl[k0 + 8], wl[k0 + 9]);
            A3[c] = h2u(wh[k0 + 8], wh[k0 + 9]);
        }
    }
    // zero own slice of h buffer 0 (fp16)
    {
        int b = b0 + (tid >> 2);
        int k = ug * 16 + (tid & 3) * 4;
        *(uint2*)&g_hst[0][dir][b][k] = make_uint2(0u, 0u);
    }
    int pb  = tid & 63;
    int pu4 = (tid >> 6) * 4;
    int pos_a = 4 * ((pu4 & 7) >> 1) + ((pu4 >= 8) ? 2 : 0);
    int pos_b = pos_a + 4;

    // prefetch xg for step 0
    {
        int t0 = dir ? T_ - 1 : 0;
        const float* xgt = xg + (size_t)t0 * (G_ * B_);
        #pragma unroll
        for (int i = 0; i < 4; i++) {
            int e = tid + i * 256;
            int r = e >> 4, boff = (e & 15) * 4;
            int grow = (r >> 4) * H_ + ug * 16 + (r & 15);
            cp16(cvta_s(XGs + r * XSF + boff), xgt + (size_t)grow * B_ + b0 + boff);
        }
        CP_COMMIT();
    }
    group_barrier(grp);

    float cst[4] = {0.f, 0.f, 0.f, 0.f};

    for (int step = 0; step < T_; step++) {
        int t = dir ? (T_ - 1 - step) : step;

        // stage h tile [64 b][256 k] fp16 via cp.async (32KB)
        #pragma unroll
        for (int i = 0; i < 8; i++) {
            int e = tid + i * 256;
            int b = e >> 5, c = e & 31;
            cp16(cvta_s(Hs + b * HS2 + c * 8), &g_hst[step & 1][dir][b0 + b][c * 8]);
        }
        CP_COMMIT();
        CP_WAIT0();     // drains Hs AND the xg prefetch
        __syncthreads();

        // acc init from xg (gates = xg + Whh*h)
        float acc[4][4];
        #pragma unroll
        for (int f = 0; f < 4; f++) {
            int col = n0 + f * 8 + 2 * tig;
            float2 lo = *(const float2*)&XGs[(m0 + gid    ) * XSF + col];
            float2 hi = *(const float2*)&XGs[(m0 + gid + 8) * XSF + col];
            acc[f][0] = lo.x; acc[f][1] = lo.y;
            acc[f][2] = hi.x; acc[f][3] = hi.y;
        }

        #pragma unroll
        for (int c = 0; c < 16; c++) {
            uint32_t a[4] = { A0[c], A1[c], A2[c], A3[c] };
            #pragma unroll
            for (int f = 0; f < 4; f++) {
                const uint32_t* bp = (const uint32_t*)(Hs + (size_t)(n0 + f*8 + gid) * HS2 + c*16 + 2*tig);
                uint32_t b2[2] = { bp[0], bp[4] };
                mma_f16(acc[f], a, b2);
            }
        }
        __syncthreads();   // Hs & XGs reads done

        // prefetch next xg (overlaps epilogue + pointwise + barrier)
        if (step + 1 < T_) {
            int tn = dir ? (T_ - 1 - (step + 1)) : (step + 1);
            const float* xgt = xg + (size_t)tn * (G_ * B_);
            #pragma unroll
            for (int i = 0; i < 4; i++) {
                int e = tid + i * 256;
                int r = e >> 4, boff = (e & 15) * 4;
                int grow = (r >> 4) * H_ + ug * 16 + (r & 15);
                cp16(cvta_s(XGs + r * XSF + boff), xgt + (size_t)grow * B_ + b0 + boff);
            }
            CP_COMMIT();
        }

        #pragma unroll
        for (int f = 0; f < 4; f++) {
            int col = n0 + f * 8 + 2 * tig;
            *(float2*)&Acc[(m0 + gid    ) * XSF + col] = make_float2(acc[f][0], acc[f][1]);
            *(float2*)&Acc[(m0 + gid + 8) * XSF + col] = make_float2(acc[f][2], acc[f][3]);
        }
        __syncthreads();

        // pointwise: thread owns (b=pb, units pu4..pu4+3)
        int nb = (step & 1) ^ 1;
        float hv[4];
        #pragma unroll
        for (int j = 0; j < 4; j++) {
            int u = pu4 + j;
            float gi = Acc[( 0 + u) * XSF + pb];
            float gf = Acc[(16 + u) * XSF + pb];
            float gg = Acc[(32 + u) * XSF + pb];
            float go = Acc[(48 + u) * XSF + pb];
            float iv = sigm_f(gi);
            float fv = sigm_f(gf);
            float gv = tanh_f(gg);
            float ov = sigm_f(go);
            cst[j] = fv * cst[j] + iv * gv;
            hv[j] = ov * tanh_f(cst[j]);
        }
        // h state (fp16, unpermuted)
        uint32_t p01 = h2u(hv[0], hv[1]);
        uint32_t p23 = h2u(hv[2], hv[3]);
        __stcg((float2*)&g_hst[nb][dir][b0 + pb][ug * 16 + pu4],
               make_float2(__uint_as_float(p01), __uint_as_float(p23)));

        if (to_ext) {
            *(float4*)(out_ext + ((size_t)t * B_ + b0 + pb) * 512 + dir * H_ + ug * 16 + pu4) =
                make_float4(hv[0], hv[1], hv[2], hv[3]);
        } else {
            __half* h0p = g_h0 + ((size_t)t * B_ + b0 + pb) * 512 + dir * 256 + ug * 16;
            *(uint32_t*)(h0p + pos_a) = p01;
            *(uint32_t*)(h0p + pos_b) = p23;
        }

        group_barrier(grp);   // h(step+1) fully visible; Acc reads done
    }
}

// ---------------- launch ----------------------------------------------------
extern "C" void kernel_launch(void* const* d_in, const int* in_sizes, int n_in,
                              void* d_out, int out_size) {
    const float* x     = (const float*)d_in[0];
    const float* wih0f = (const float*)d_in[1];
    const float* whh0f = (const float*)d_in[2];
    const float* bih0f = (const float*)d_in[3];
    const float* bhh0f = (const float*)d_in[4];
    const float* wih0b = (const float*)d_in[5];
    const float* whh0b = (const float*)d_in[6];
    const float* bih0b = (const float*)d_in[7];
    const float* bhh0b = (const float*)d_in[8];
    const float* wih1f = (const float*)d_in[9];
    const float* whh1f = (const float*)d_in[10];
    const float* bih1f = (const float*)d_in[11];
    const float* bhh1f = (const float*)d_in[12];
    const float* wih1b = (const float*)d_in[13];
    const float* whh1b = (const float*)d_in[14];
    const float* bih1b = (const float*)d_in[15];
    const float* bhh1b = (const float*)d_in[16];
    float* out = (float*)d_out;

    cudaFuncSetAttribute(gemm_xg, cudaFuncAttributeMaxDynamicSharedMemorySize, GEMM_SMEM);
    cudaFuncSetAttribute(lstm_rec_mma, cudaFuncAttributeMaxDynamicSharedMemorySize, REC_SMEM);

    prep_round<<<1024, 256>>>(x, wih0f, wih0b, wih1f, wih1b);

    dim3 gg(2, 16, T_);
    gemm_xg<<<gg, 128, GEMM_SMEM>>>(0, bih0f, bhh0f, bih0b, bhh0b);
    lstm_rec_mma<<<128, 256, REC_SMEM>>>(whh0f, whh0b, out, 0);
    gemm_xg<<<gg, 128, GEMM_SMEM>>>(1, bih1f, bhh1f, bih1b, bhh1b);
    lstm_rec_mma<<<128, 256, REC_SMEM>>>(whh1f, whh1b, out, 1);
}

// round 17
// speedup vs baseline: 1.0961x; 1.0961x over previous
#include <cuda_runtime.h>
#include <cuda_fp16.h>
#include <math.h>
#include <stdint.h>

// Problem dims
#define T_ 160
#define B_ 256
#define H_ 256
#define G_ 1024   // 4H
#define K_ 512    // Cin for both layers

// ---------------- scratch (device globals) ----------------------------------
__device__ __half g_xr [(size_t)T_ * B_ * K_];    // x -> fp16, k16-permuted
__device__ __half g_wr [4][(size_t)G_ * K_];      // Wih l0f,l0b,l1f,l1b fp16, permuted
__device__ float  g_xgf[(size_t)T_ * G_ * B_];    // [T,4H,B] fwd (fp32 gates)
__device__ float  g_xgb[(size_t)T_ * G_ * B_];    // [T,4H,B] bwd
__device__ __half g_h0 [(size_t)T_ * B_ * 512];   // layer-0 out, fp16, permuted
__device__ __half g_hst[2][2][B_][H_];            // h state fp16 [buf][dir][b][k]
__device__ unsigned g_rcnt[8][32];                // gen-barrier (proven R4/R6/R7)
__device__ volatile unsigned g_rgen[8][32];

// ---------------- helpers ---------------------------------------------------
__device__ __forceinline__ void mma_f16(float c[4], const uint32_t a[4], const uint32_t b[2]) {
    asm volatile(
        "mma.sync.aligned.m16n8k16.row.col.f32.f16.f16.f32 "
        "{%0,%1,%2,%3}, {%4,%5,%6,%7}, {%8,%9}, {%0,%1,%2,%3};"
        : "+f"(c[0]), "+f"(c[1]), "+f"(c[2]), "+f"(c[3])
        : "r"(a[0]), "r"(a[1]), "r"(a[2]), "r"(a[3]), "r"(b[0]), "r"(b[1]));
}
__device__ __forceinline__ uint32_t cvta_s(const void* p) {
    return (uint32_t)__cvta_generic_to_shared(p);
}
__device__ __forceinline__ void cp16(uint32_t s, const void* g) {
    asm volatile("cp.async.cg.shared.global [%0], [%1], 16;\n" :: "r"(s), "l"(g));
}
#define CP_COMMIT() asm volatile("cp.async.commit_group;\n")
#define CP_WAIT0()  asm volatile("cp.async.wait_group 0;\n")
#define CP_WAIT1()  asm volatile("cp.async.wait_group 1;\n")
#define CP_WAIT2()  asm volatile("cp.async.wait_group 2;\n")

__device__ __forceinline__ float sigm_f(float x) {
    return __fdividef(1.f, 1.f + __expf(-x));
}
__device__ __forceinline__ float tanh_f(float x) {
    float e = __expf(2.f * x);
    return (e - 1.f) * __fdividef(1.f, e + 1.f);
}
__device__ __forceinline__ uint32_t h2u(float a, float b) {
    __half2 h = __floats2half2_rn(a, b);
    return *(uint32_t*)&h;
}

// 16-CTA group barrier (CTAs sharing dir+batch-tile) — proven R4/R6/R7
__device__ __forceinline__ void group_barrier(int grp) {
    __syncthreads();
    if (threadIdx.x == 0) {
        unsigned gen = g_rgen[grp][0];
        __threadfence();
        if (atomicAdd(&g_rcnt[grp][0], 1) == 15) {
            g_rcnt[grp][0] = 0;
            __threadfence();
            g_rgen[grp][0] = gen + 1;
        } else {
            while (g_rgen[grp][0] == gen) { }
        }
        __threadfence();
    }
    __syncthreads();
}

// ---------------- prep: fp16-convert x + Wih with k16 permutation -----------
__device__ __forceinline__ void perm_store8(__half* dst, const float* src16, int q0) {
    __half h[8];
    int t0 = q0 >> 2;
    #pragma unroll
    for (int j = 0; j < 2; j++) {
        int t = t0 + j;
        h[j*4+0] = __float2half_rn(src16[2*t]);
        h[j*4+1] = __float2half_rn(src16[2*t+1]);
        h[j*4+2] = __float2half_rn(src16[8+2*t]);
        h[j*4+3] = __float2half_rn(src16[9+2*t]);
    }
    *(uint4*)(dst + q0) = *(uint4*)h;
}

__global__ void prep_round(const float* __restrict__ x,
                           const float* __restrict__ w0f, const float* __restrict__ w0b,
                           const float* __restrict__ w1f, const float* __restrict__ w1b)
{
    size_t i0 = (size_t)blockIdx.x * blockDim.x + threadIdx.x;
    size_t stride = (size_t)gridDim.x * blockDim.x;
    const size_t NX8 = (size_t)T_ * B_ * K_ / 8;
    const size_t NW8 = (size_t)G_ * K_ / 8;
    for (size_t e = i0; e < NX8; e += stride) {
        size_t row = e >> 6;
        int off8 = (int)(e & 63) * 8;
        int blk = off8 >> 4, sub = off8 & 15;
        perm_store8(g_xr + row * K_ + blk * 16, x + row * K_ + blk * 16, sub);
    }
    const float* ws[4] = { w0f, w0b, w1f, w1b };
    #pragma unroll
    for (int l = 0; l < 4; l++) {
        for (size_t e = i0; e < NW8; e += stride) {
            size_t row = e >> 6;
            int off8 = (int)(e & 63) * 8;
            int blk = off8 >> 4, sub = off8 & 15;
            perm_store8(g_wr[l] + row * K_ + blk * 16, ws[l] + row * K_ + blk * 16, sub);
        }
    }
}

// ---------------- input GEMM: fp16 m16n8k16, warp 64x64, 3-stage (R7) -------
#define GS2 48
#define GEMM_STAGE (2 * 128 * GS2)
#define GEMM_SMEM (3 * GEMM_STAGE * 2)

__global__ __launch_bounds__(128, 2) void gemm_xg(
    int layer,
    const float* __restrict__ bif, const float* __restrict__ bhf,
    const float* __restrict__ bib, const float* __restrict__ bhb)
{
    extern __shared__ __half gsm[];
    const __half* X = layer ? g_h0 : g_xr;

    int t  = blockIdx.z;
    int jt = blockIdx.y;
    int bt = blockIdx.x;
    int dir = jt >> 3;
    int j0  = (jt & 7) * 128;
    int b0  = bt * 128;
    const __half* W  = g_wr[layer * 2 + dir];
    const float* bi = dir ? bib : bif;
    const float* bh = dir ? bhb : bhf;
    float* out = dir ? g_xgb : g_xgf;

    int tid  = threadIdx.x;
    int wid  = tid >> 5;
    int lane = tid & 31;
    int gid  = lane >> 2;
    int tig  = lane & 3;
    int m0   = (wid >> 1) * 64;
    int n0   = (wid & 1) * 64;

    const __half* Xb = X + ((size_t)t * B_ + b0) * K_;
    const __half* Wb = W + (size_t)j0 * K_;

    float acc[4][8][4];
    #pragma unroll
    for (int mi = 0; mi < 4; mi++)
        #pragma unroll
        for (int ni = 0; ni < 8; ni++)
            #pragma unroll
            for (int r = 0; r < 4; r++) acc[mi][ni][r] = 0.f;

    #pragma unroll
    for (int ps = 0; ps < 2; ps++) {
        __half* As = gsm + ps * GEMM_STAGE;
        __half* Bs = As + 128 * GS2;
        int k0 = ps * 32;
        #pragma unroll
        for (int i = 0; i < 4; i++) {
            int e = tid + i * 128;
            int row = e >> 2, c = e & 3;
            cp16(cvta_s(As + row * GS2 + c * 8), Wb + (size_t)row * K_ + k0 + c * 8);
            cp16(cvta_s(Bs + row * GS2 + c * 8), Xb + (size_t)row * K_ + k0 + c * 8);
        }
        CP_COMMIT();
    }

    for (int s = 0; s < 16; s++) {
        if (s < 15) { CP_WAIT1(); } else { CP_WAIT0(); }
        __syncthreads();

        if (s + 2 < 16) {
            int k0 = (s + 2) * 32;
            __half* As = gsm + ((s + 2) % 3) * GEMM_STAGE;
            __half* Bs = As + 128 * GS2;
            #pragma unroll
            for (int i = 0; i < 4; i++) {
                int e = tid + i * 128;
                int row = e >> 2, c = e & 3;
                cp16(cvta_s(As + row * GS2 + c * 8), Wb + (size_t)row * K_ + k0 + c * 8);
                cp16(cvta_s(Bs + row * GS2 + c * 8), Xb + (size_t)row * K_ + k0 + c * 8);
            }
            CP_COMMIT();
        }

        const __half* As = gsm + (s % 3) * GEMM_STAGE;
        const __half* Bs = As + 128 * GS2;

        #pragma unroll
        for (int c = 0; c < 2; c++) {
            uint32_t a[4][4];
            #pragma unroll
            for (int mi = 0; mi < 4; mi++) {
                uint2 al = *(const uint2*)(As + (m0 + mi*16 + gid    ) * GS2 + c*16 + tig*4);
                uint2 ah = *(const uint2*)(As + (m0 + mi*16 + gid + 8) * GS2 + c*16 + tig*4);
                a[mi][0] = al.x; a[mi][1] = ah.x; a[mi][2] = al.y; a[mi][3] = ah.y;
            }
            uint32_t b[8][2];
            #pragma unroll
            for (int ni = 0; ni < 8; ni++) {
                uint2 bv = *(const uint2*)(Bs + (n0 + ni*8 + gid) * GS2 + c*16 + tig*4);
                b[ni][0] = bv.x; b[ni][1] = bv.y;
            }
            #pragma unroll
            for (int mi = 0; mi < 4; mi++)
                #pragma unroll
                for (int ni = 0; ni < 8; ni++)
                    mma_f16(acc[mi][ni], a[mi], b[ni]);
        }
    }

    #pragma unroll
    for (int mi = 0; mi < 4; mi++) {
        int j_lo = j0 + m0 + mi * 16 + gid;
        int j_hi = j_lo + 8;
        float bs_lo = bi[j_lo] + bh[j_lo];
        float bs_hi = bi[j_hi] + bh[j_hi];
        #pragma unroll
        for (int ni = 0; ni < 8; ni++) {
            int bc = b0 + n0 + ni * 8 + 2 * tig;
            float2 lo = make_float2(acc[mi][ni][0] + bs_lo, acc[mi][ni][1] + bs_lo);
            float2 hi = make_float2(acc[mi][ni][2] + bs_hi, acc[mi][ni][3] + bs_hi);
            *(float2*)(out + ((size_t)t * G_ + j_lo) * B_ + bc) = lo;
            *(float2*)(out + ((size_t)t * G_ + j_hi) * B_ + bc) = hi;
        }
    }
}

// ---------------- recurrence: fp16 MMA, pipelined staging, gen-barrier ------
// 128 CTAs: dir=bid>>6, ug=(bid>>2)&15 (16 units), bt=bid&3 (64 batch).
#define HS2 264                                  // halves per Hs row
#define XSF 68                                   // floats per XGs row
#define HS_BYTES (64 * HS2 * 2)                  // 33792
#define REC_SMEM (HS_BYTES + 64 * XSF * 4)       // + 17408 = 51200

__global__ void __launch_bounds__(256, 1) lstm_rec_mma(
    const float* __restrict__ Whhf, const float* __restrict__ Whhb,
    float* __restrict__ out_ext, int to_ext)
{
    extern __shared__ __align__(16) char sm[];
    __half* Hs  = (__half*)sm;                   // [64 b][HS2]
    float*  XGs = (float*)(sm + HS_BYTES);       // [64 gate-row][XSF]
    float*  Acc = (float*)sm;                    // alias over Hs after MMA  [64][XSF]

    int bid = blockIdx.x;
    int dir = bid >> 6;
    int ug  = (bid >> 2) & 15;
    int bt  = bid & 3;
    int b0  = bt * 64;
    int grp = dir * 4 + bt;
    int tid = threadIdx.x;
    int wid = tid >> 5, lane = tid & 31, gid = lane >> 2, tig = lane & 3;
    int m0 = (wid >> 1) * 16;
    int n0 = (wid & 1) * 32;
    const float* Whh = dir ? Whhb : Whhf;
    const float* xg  = dir ? g_xgb : g_xgf;

    // W fragments -> registers as fp16 (rounded once). 16 k16-chunks x 4 regs.
    uint32_t A0[16], A1[16], A2[16], A3[16];
    {
        int rl = m0 + gid, rh = rl + 8;
        const float* wl = Whh + (size_t)((rl >> 4) * H_ + ug * 16 + (rl & 15)) * H_;
        const float* wh = Whh + (size_t)((rh >> 4) * H_ + ug * 16 + (rh & 15)) * H_;
        #pragma unroll
        for (int c = 0; c < 16; c++) {
            int k0 = c * 16 + 2 * tig;
            A0[c] = h2u(wl[k0],     wl[k0 + 1]);
            A1[c] = h2u(wh[k0],     wh[k0 + 1]);
            A2[c] = h2u(wl[k0 + 8], wl[k0 + 9]);
            A3[c] = h2u(wh[k0 + 8], wh[k0 + 9]);
        }
    }
    // zero own slice of h buffer 0 (fp16)
    {
        int b = b0 + (tid >> 2);
        int k = ug * 16 + (tid & 3) * 4;
        *(uint2*)&g_hst[0][dir][b][k] = make_uint2(0u, 0u);
    }
    int pb  = tid & 63;
    int pu4 = (tid >> 6) * 4;
    int pos_a = 4 * ((pu4 & 7) >> 1) + ((pu4 >= 8) ? 2 : 0);
    int pos_b = pos_a + 4;

    // prefetch xg for step 0 (own commit group; stays oldest pending)
    {
        int t0 = dir ? T_ - 1 : 0;
        const float* xgt = xg + (size_t)t0 * (G_ * B_);
        #pragma unroll
        for (int i = 0; i < 4; i++) {
            int e = tid + i * 256;
            int r = e >> 4, boff = (e & 15) * 4;
            int grow = (r >> 4) * H_ + ug * 16 + (r & 15);
            cp16(cvta_s(XGs + r * XSF + boff), xgt + (size_t)grow * B_ + b0 + boff);
        }
        CP_COMMIT();
    }
    group_barrier(grp);

    float cst[4] = {0.f, 0.f, 0.f, 0.f};

    for (int step = 0; step < T_; step++) {
        int t = dir ? (T_ - 1 - step) : step;

        // stage h tile in two k-halves (separate commit groups)
        #pragma unroll
        for (int i = 0; i < 4; i++) {            // half 1: k 0..127
            int e = tid + i * 256;
            int b = e >> 4, c = e & 15;
            cp16(cvta_s(Hs + b * HS2 + c * 8), &g_hst[step & 1][dir][b0 + b][c * 8]);
        }
        CP_COMMIT();                             // group H1
        #pragma unroll
        for (int i = 0; i < 4; i++) {            // half 2: k 128..255
            int e = tid + i * 256;
            int b = e >> 4, c = e & 15;
            cp16(cvta_s(Hs + b * HS2 + 128 + c * 8), &g_hst[step & 1][dir][b0 + b][128 + c * 8]);
        }
        CP_COMMIT();                             // group H2
        // pending: [XG(old), H1, H2]

        CP_WAIT2();                              // XG done
        __syncthreads();

        // acc init from xg (gates = xg + Whh*h) — overlaps H1/H2 in flight
        float acc[4][4];
        #pragma unroll
        for (int f = 0; f < 4; f++) {
            int col = n0 + f * 8 + 2 * tig;
            float2 lo = *(const float2*)&XGs[(m0 + gid    ) * XSF + col];
            float2 hi = *(const float2*)&XGs[(m0 + gid + 8) * XSF + col];
            acc[f][0] = lo.x; acc[f][1] = lo.y;
            acc[f][2] = hi.x; acc[f][3] = hi.y;
        }

        CP_WAIT1();                              // H1 done
        __syncthreads();

        #pragma unroll
        for (int c = 0; c < 8; c++) {            // MMA on k 0..127
            uint32_t a[4] = { A0[c], A1[c], A2[c], A3[c] };
            #pragma unroll
            for (int f = 0; f < 4; f++) {
                const uint32_t* bp = (const uint32_t*)(Hs + (size_t)(n0 + f*8 + gid) * HS2 + c*16 + 2*tig);
                uint32_t b2[2] = { bp[0], bp[4] };
                mma_f16(acc[f], a, b2);
            }
        }

        CP_WAIT0();                              // H2 done
        __syncthreads();

        #pragma unroll
        for (int c = 8; c < 16; c++) {           // MMA on k 128..255
            uint32_t a[4] = { A0[c], A1[c], A2[c], A3[c] };
            #pragma unroll
            for (int f = 0; f < 4; f++) {
                const uint32_t* bp = (const uint32_t*)(Hs + (size_t)(n0 + f*8 + gid) * HS2 + c*16 + 2*tig);
                uint32_t b2[2] = { bp[0], bp[4] };
                mma_f16(acc[f], a, b2);
            }
        }
        __syncthreads();   // Hs & XGs reads done

        // prefetch next xg (own group; overlaps epilogue + pointwise + barrier)
        if (step + 1 < T_) {
            int tn = dir ? (T_ - 1 - (step + 1)) : (step + 1);
            const float* xgt = xg + (size_t)tn * (G_ * B_);
            #pragma unroll
            for (int i = 0; i < 4; i++) {
                int e = tid + i * 256;
                int r = e >> 4, boff = (e & 15) * 4;
                int grow = (r >> 4) * H_ + ug * 16 + (r & 15);
                cp16(cvta_s(XGs + r * XSF + boff), xgt + (size_t)grow * B_ + b0 + boff);
            }
            CP_COMMIT();
        }

        #pragma unroll
        for (int f = 0; f < 4; f++) {
            int col = n0 + f * 8 + 2 * tig;
            *(float2*)&Acc[(m0 + gid    ) * XSF + col] = make_float2(acc[f][0], acc[f][1]);
            *(float2*)&Acc[(m0 + gid + 8) * XSF + col] = make_float2(acc[f][2], acc[f][3]);
        }
        __syncthreads();

        // pointwise: thread owns (b=pb, units pu4..pu4+3)
        int nb = (step & 1) ^ 1;
        float hv[4];
        #pragma unroll
        for (int j = 0; j < 4; j++) {
            int u = pu4 + j;
            float gi = Acc[( 0 + u) * XSF + pb];
            float gf = Acc[(16 + u) * XSF + pb];
            float gg = Acc[(32 + u) * XSF + pb];
            float go = Acc[(48 + u) * XSF + pb];
            float iv = sigm_f(gi);
            float fv = sigm_f(gf);
            float gv = tanh_f(gg);
            float ov = sigm_f(go);
            cst[j] = fv * cst[j] + iv * gv;
            hv[j] = ov * tanh_f(cst[j]);
        }
        // h state (fp16, unpermuted)
        uint32_t p01 = h2u(hv[0], hv[1]);
        uint32_t p23 = h2u(hv[2], hv[3]);
        __stcg((float2*)&g_hst[nb][dir][b0 + pb][ug * 16 + pu4],
               make_float2(__uint_as_float(p01), __uint_as_float(p23)));

        if (to_ext) {
            *(float4*)(out_ext + ((size_t)t * B_ + b0 + pb) * 512 + dir * H_ + ug * 16 + pu4) =
                make_float4(hv[0], hv[1], hv[2], hv[3]);
        } else {
            __half* h0p = g_h0 + ((size_t)t * B_ + b0 + pb) * 512 + dir * 256 + ug * 16;
            *(uint32_t*)(h0p + pos_a) = p01;
            *(uint32_t*)(h0p + pos_b) = p23;
        }

        group_barrier(grp);   // h(step+1) fully visible; Acc reads done
    }
}

// ---------------- launch ----------------------------------------------------
extern "C" void kernel_launch(void* const* d_in, const int* in_sizes, int n_in,
                              void* d_out, int out_size) {
    const float* x     = (const float*)d_in[0];
    const float* wih0f = (const float*)d_in[1];
    const float* whh0f = (const float*)d_in[2];
    const float* bih0f = (const float*)d_in[3];
    const float* bhh0f = (const float*)d_in[4];
    const float* wih0b = (const float*)d_in[5];
    const float* whh0b = (const float*)d_in[6];
    const float* bih0b = (const float*)d_in[7];
    const float* bhh0b = (const float*)d_in[8];
    const float* wih1f = (const float*)d_in[9];
    const float* whh1f = (const float*)d_in[10];
    const float* bih1f = (const float*)d_in[11];
    const float* bhh1f = (const float*)d_in[12];
    const float* wih1b = (const float*)d_in[13];
    const float* whh1b = (const float*)d_in[14];
    const float* bih1b = (const float*)d_in[15];
    const float* bhh1b = (const float*)d_in[16];
    float* out = (float*)d_out;

    cudaFuncSetAttribute(gemm_xg, cudaFuncAttributeMaxDynamicSharedMemorySize, GEMM_SMEM);
    cudaFuncSetAttribute(lstm_rec_mma, cudaFuncAttributeMaxDynamicSharedMemorySize, REC_SMEM);

    prep_round<<<1024, 256>>>(x, wih0f, wih0b, wih1f, wih1b);

    dim3 gg(2, 16, T_);
    gemm_xg<<<gg, 128, GEMM_SMEM>>>(0, bih0f, bhh0f, bih0b, bhh0b);
    lstm_rec_mma<<<128, 256, REC_SMEM>>>(whh0f, whh0b, out, 0);
    gemm_xg<<<gg, 128, GEMM_SMEM>>>(1, bih1f, bhh1f, bih1b, bhh1b);
    lstm_rec_mma<<<128, 256, REC_SMEM>>>(whh1f, whh1b, out, 1);
}